// round 15
// baseline (speedup 1.0000x reference)
#include <cuda_runtime.h>
#include <cuda_bf16.h>
#include <math.h>
#include <stdint.h>

#define N_NODES 200000
#define C_INN   256
#define C_MID   64
#define KNB     27
#define BN_EPS  1e-3f

// ---------------- scratch (device globals; no allocations allowed) ----------
__device__ float g_y1[(size_t)N_NODES * C_MID];   // x@W1 (fp32)
__device__ float g_y2[(size_t)N_NODES * C_MID];   // gathered conv out
__device__ float g_y3[(size_t)N_NODES * C_INN];   // h2@W3
__device__ unsigned int g_h1pack[(size_t)N_NODES * C_MID];   // (hi<<16)|lo bf16 of relu(bn1(y1))
// weights in m16n8k16 B-fragment order: [hi/lo][(kstep*Nj + j)*32 + lane] uint4
__device__ __align__(16) uint4 g_w2f[2][KNB * 4 * 4 * 32];
__device__ __align__(16) uint4 g_w1f[2][16 * 4 * 32];
__device__ __align__(16) uint4 g_w3f[2][4 * 16 * 32];
// stats layout: [0:64) sum1 [64:128) sq1 [128:192) sum2 [192:256) sq2
//               [256:512) sum3 [512:768) sq3
__device__ float g_stats[768];

// ======================= warp-MMA helpers (plain sm_103 PTX) =================
__device__ __forceinline__ uint32_t smem_u32(const void* p) {
    uint32_t a;
    asm("{ .reg .u64 t; cvta.to.shared.u64 t, %1; cvt.u32.u64 %0, t; }" : "=r"(a) : "l"(p));
    return a;
}
__device__ __forceinline__ uint32_t sw128(uint32_t off) { return off ^ ((off >> 3) & 0x70); }

__device__ __forceinline__ void ldsm4(uint32_t* r, uint32_t addr) {
    asm volatile("ldmatrix.sync.aligned.m8n8.x4.shared.b16 {%0,%1,%2,%3}, [%4];"
                 : "=r"(r[0]), "=r"(r[1]), "=r"(r[2]), "=r"(r[3]) : "r"(addr));
}
__device__ __forceinline__ void mma16816(float* d, const uint32_t* a, uint32_t b0, uint32_t b1) {
    asm volatile("mma.sync.aligned.m16n8k16.row.col.f32.bf16.bf16.f32 "
                 "{%0,%1,%2,%3}, {%4,%5,%6,%7}, {%8,%9}, {%0,%1,%2,%3};"
                 : "+f"(d[0]), "+f"(d[1]), "+f"(d[2]), "+f"(d[3])
                 : "r"(a[0]), "r"(a[1]), "r"(a[2]), "r"(a[3]), "r"(b0), "r"(b1));
}
__device__ __forceinline__ void bf16split(float v, unsigned short& h, unsigned short& l) {
    __nv_bfloat16 hb = __float2bfloat16(v);
    h = __bfloat16_as_ushort(hb);
    l = __bfloat16_as_ushort(__float2bfloat16(v - __bfloat162float(hb)));
}
__device__ __forceinline__ void cp_async16(uint32_t dst, const void* src) {
    asm volatile("cp.async.cg.shared.global [%0], [%1], 16;" :: "r"(dst), "l"(src));
}
#define CP_COMMIT() asm volatile("cp.async.commit_group;" ::: "memory")
#define CP_WAIT1()  asm volatile("cp.async.wait_group 1;" ::: "memory")
#define CP_WAIT0()  asm volatile("cp.async.wait_group 0;" ::: "memory")

__device__ __forceinline__ uint2 lds64(uint32_t addr) {
    uint2 v;
    asm volatile("ld.shared.v2.u32 {%0,%1}, [%2];" : "=r"(v.x), "=r"(v.y) : "r"(addr));
    return v;
}
__device__ __forceinline__ uint4 lds128(uint32_t addr) {
    uint4 v;
    asm volatile("ld.shared.v4.u32 {%0,%1,%2,%3}, [%4];"
                 : "=r"(v.x), "=r"(v.y), "=r"(v.z), "=r"(v.w) : "r"(addr));
    return v;
}

// -------- weight fragment packer (m16n8k16 B-frag order, verified) ----------
__device__ __forceinline__ void pack_frag(const float* __restrict__ W, int ldw,
                                          int c0, int n0, uint4* hi4, uint4* lo4) {
    unsigned int hi[4], lo[4];
    #pragma unroll
    for (int q = 0; q < 4; q++) {
        int c = c0 + (q & 1) * 8;
        int n = n0 + (q >> 1) * 8;
        float v0 = W[c * ldw + n];
        float v1 = W[(c + 1) * ldw + n];
        unsigned short h0, l0, h1, l1;
        bf16split(v0, h0, l0);
        bf16split(v1, h1, l1);
        hi[q] = ((unsigned int)h1 << 16) | h0;
        lo[q] = ((unsigned int)l1 << 16) | l0;
    }
    *hi4 = make_uint4(hi[0], hi[1], hi[2], hi[3]);
    *lo4 = make_uint4(lo[0], lo[1], lo[2], lo[3]);
}

// ---------------- convert_all: pack W1/W2/W3 frags + zero stats -------------
__global__ void convert_all_kernel(const float* __restrict__ W1,
                                   const float* __restrict__ W2,
                                   const float* __restrict__ W3) {
    int b = blockIdx.x, t = threadIdx.x;    // 512 threads
    if (b == 0) {
        for (int i = t; i < 768; i += 512) g_stats[i] = 0.f;
    }
    if (b < 27) {
        int kk = t >> 7, j = (t >> 5) & 3, lane = t & 31;
        int idx = ((b * 4 + kk) * 4 + j) * 32 + lane;
        pack_frag(W2 + (size_t)b * 4096, 64,
                  kk * 16 + (lane & 3) * 2, j * 16 + (lane >> 2),
                  &g_w2f[0][idx], &g_w2f[1][idx]);
    } else if (b < 31) {
        int gt = (b - 27) * 512 + t;
        int kk = gt >> 7, j = (gt >> 5) & 3, lane = gt & 31;
        int idx = (kk * 4 + j) * 32 + lane;
        pack_frag(W1, 64, kk * 16 + (lane & 3) * 2, j * 16 + (lane >> 2),
                  &g_w1f[0][idx], &g_w1f[1][idx]);
    } else {
        int gt = (b - 31) * 512 + t;
        int kk = gt >> 9, j = (gt >> 5) & 15, lane = gt & 31;
        int idx = (kk * 16 + j) * 32 + lane;
        pack_frag(W3, 256, kk * 16 + (lane & 3) * 2, j * 16 + (lane >> 2),
                  &g_w3f[0][idx], &g_w3f[1][idx]);
    }
}

// ---------------- GEMM1 (warp MMA): y1 = x @ W1, fused stats1 ---------------
#define G1_SUM  32768
#define G1_SMEM (G1_SUM + 512)
__global__ __launch_bounds__(256, 2)
void gemm1_mma_kernel(const float* __restrict__ x) {
    extern __shared__ char smc[];
    float* s_sum = (float*)(smc + G1_SUM);
    float* s_sq  = s_sum + 64;
    const int t = threadIdx.x, w = t >> 5, lane = t & 31;
    const int n0 = blockIdx.x * 128;
    if (t < 64) { s_sum[t] = 0.f; s_sq[t] = 0.f; }
    __syncthreads();

    float acc[8][4];
    #pragma unroll
    for (int nt = 0; nt < 8; nt++)
        #pragma unroll
        for (int i = 0; i < 4; i++) acc[nt][i] = 0.f;

    char* Aw_hi = smc + w * 4096;
    char* Aw_lo = Aw_hi + 2048;
    const uint32_t a_hi_u = smem_u32(Aw_hi);
    const uint32_t a_lo_u = a_hi_u + 2048;

    const int glr = lane >> 1, ghalf = lane & 1;
    const int row = n0 + w * 16 + glr;
    const int rowc = row < N_NODES ? row : N_NODES - 1;
    const float4* xsrc = (const float4*)(x + (size_t)rowc * C_INN + ghalf * 32);

    float4 f[8];
    #pragma unroll
    for (int i = 0; i < 8; i++) f[i] = __ldg(xsrc + i);

    #pragma unroll
    for (int kc = 0; kc < 4; kc++) {
        #pragma unroll
        for (int i = 0; i < 8; i++) {
            unsigned short hx, lx, hy, ly, hz, lz, hw, lw;
            bf16split(f[i].x, hx, lx);
            bf16split(f[i].y, hy, ly);
            bf16split(f[i].z, hz, lz);
            bf16split(f[i].w, hw, lw);
            uint32_t off = sw128((uint32_t)(glr * 128 + ghalf * 64 + i * 8));
            *(uint2*)(Aw_hi + off) = make_uint2(((uint32_t)hy << 16) | hx,
                                                ((uint32_t)hw << 16) | hz);
            *(uint2*)(Aw_lo + off) = make_uint2(((uint32_t)ly << 16) | lx,
                                                ((uint32_t)lw << 16) | lz);
        }
        __syncwarp();
        if (kc < 3) {
            #pragma unroll
            for (int i = 0; i < 8; i++) f[i] = __ldg(xsrc + (kc + 1) * 16 + i);
        }
        #pragma unroll
        for (int kk = 0; kk < 4; kk++) {
            uint32_t ah[4], al[4];
            uint32_t aoff = sw128((uint32_t)((lane & 15) * 128 + kk * 32 + (lane >> 4) * 16));
            ldsm4(ah, a_hi_u + aoff);
            ldsm4(al, a_lo_u + aoff);
            #pragma unroll
            for (int j = 0; j < 4; j++) {
                uint4 Bh = __ldg(&g_w1f[0][((kc * 4 + kk) * 4 + j) * 32 + lane]);
                uint4 Bl = __ldg(&g_w1f[1][((kc * 4 + kk) * 4 + j) * 32 + lane]);
                mma16816(acc[2 * j],     ah, Bh.x, Bh.y);
                mma16816(acc[2 * j + 1], ah, Bh.z, Bh.w);
                mma16816(acc[2 * j],     al, Bh.x, Bh.y);
                mma16816(acc[2 * j + 1], al, Bh.z, Bh.w);
                mma16816(acc[2 * j],     ah, Bl.x, Bl.y);
                mma16816(acc[2 * j + 1], ah, Bl.z, Bl.w);
            }
        }
        __syncwarp();
    }

    const int rA = w * 16 + (lane >> 2);
    const int nodeA = n0 + rA, nodeB = nodeA + 8;
    const bool okA = nodeA < N_NODES, okB = nodeB < N_NODES;
    const int col0 = (lane & 3) * 2;
    #pragma unroll
    for (int nt = 0; nt < 8; nt++) {
        int c = nt * 8 + col0;
        if (okA) *(float2*)(g_y1 + (size_t)nodeA * C_MID + c) = make_float2(acc[nt][0], acc[nt][1]);
        if (okB) *(float2*)(g_y1 + (size_t)nodeB * C_MID + c) = make_float2(acc[nt][2], acc[nt][3]);
        float v0 = okA ? acc[nt][0] : 0.f, v1 = okA ? acc[nt][1] : 0.f;
        float v2 = okB ? acc[nt][2] : 0.f, v3 = okB ? acc[nt][3] : 0.f;
        float s0 = v0 + v2, s1 = v1 + v3;
        float q0 = v0 * v0 + v2 * v2, q1 = v1 * v1 + v3 * v3;
        #pragma unroll
        for (int o = 4; o < 32; o <<= 1) {
            s0 += __shfl_xor_sync(0xFFFFFFFF, s0, o);
            s1 += __shfl_xor_sync(0xFFFFFFFF, s1, o);
            q0 += __shfl_xor_sync(0xFFFFFFFF, q0, o);
            q1 += __shfl_xor_sync(0xFFFFFFFF, q1, o);
        }
        if (lane < 4) {
            atomicAdd(&s_sum[c],     s0);
            atomicAdd(&s_sum[c + 1], s1);
            atomicAdd(&s_sq[c],      q0);
            atomicAdd(&s_sq[c + 1],  q1);
        }
    }
    __syncthreads();
    if (t < 64) {
        atomicAdd(&g_stats[t],      s_sum[t]);
        atomicAdd(&g_stats[64 + t], s_sq[t]);
    }
}

// ---------------- convert h1: per-block BN1 finalize + pack bf16 hi/lo ------
__global__ void convert_h1_kernel(const float* __restrict__ gamma,
                                  const float* __restrict__ beta) {
    __shared__ float s_sc[64], s_sh[64];
    const int tt = threadIdx.x;
    if (tt < 64) {
        const float inv_n = 1.0f / (float)N_NODES;
        float mean = g_stats[tt] * inv_n;
        float var  = g_stats[64 + tt] * inv_n - mean * mean;
        float sc   = gamma[tt] * rsqrtf(var + BN_EPS);
        s_sc[tt] = sc;
        s_sh[tt] = beta[tt] - mean * sc;
    }
    __syncthreads();
    size_t i = (size_t)blockIdx.x * blockDim.x + tt;   // one float4
    if (i >= (size_t)N_NODES * (C_MID / 4)) return;
    int c0 = ((int)(i & 15)) << 2;
    float4 y = ((const float4*)g_y1)[i];
    float v[4] = {y.x, y.y, y.z, y.w};
    uint4 o;
    unsigned int* op = (unsigned int*)&o;
    #pragma unroll
    for (int j = 0; j < 4; j++) {
        float h = fmaxf(fmaf(v[j], s_sc[c0 + j], s_sh[c0 + j]), 0.f);
        unsigned short hb, lb;
        bf16split(h, hb, lb);
        op[j] = ((unsigned int)hb << 16) | lb;
    }
    ((uint4*)g_h1pack)[i] = o;
}

// ---------------- GEMM2 v6: cp.async A gather + cp.async B smem stages ------
// CTA = 128 rows, 8 warps x 16 rows, 2 CTAs/SM. A: per-warp 2-stage gather
// (R9-proven addressing). B: 16KB fragment tile per neighbor staged in smem
// via CTA-cooperative cp.async (double-buffered) -> B reads become 29-cyc
// conflict-free LDS.128 instead of ~240-cyc L2 LDG (L1 is starved by the
// 2x112KB smem carveout, measured R12: issue 14%, nothing saturated).
// Barriers per k: wait_group -> __syncthreads (consume), __syncthreads
// (reads done) -> issue k+2 into the freed stage.
#define G2_IDX   0
#define G2_A     13824                  // 8 warps x 2 stages x 4096 = 65536
#define G2_B     (G2_A + 65536)         // 2 stages x 16384 = 32768
#define G2_SUM   (G2_B + 32768)         // 112128
#define G2_SMEM  (G2_SUM + 512)         // 112640
#define G2_BLOCKS ((N_NODES + 127) / 128)   // 1563

__global__ __launch_bounds__(256, 2)
void gemm2_mma_kernel(const int* __restrict__ neigh) {
    extern __shared__ char smc[];
    int*   s_idx = (int*)(smc + G2_IDX);
    float* s_sum = (float*)(smc + G2_SUM);
    float* s_sq  = s_sum + 64;

    const int t = threadIdx.x, w = t >> 5, lane = t & 31;
    const int n0 = blockIdx.x * 128;

    for (int i = t; i < 128 * KNB; i += 256) {
        size_t gi = (size_t)n0 * KNB + i;
        s_idx[i] = (gi < (size_t)N_NODES * KNB) ? neigh[gi] : 0;
    }
    if (t < 64) { s_sum[t] = 0.f; s_sq[t] = 0.f; }
    __syncthreads();

    float acc[8][4];
    #pragma unroll
    for (int nt = 0; nt < 8; nt++)
        #pragma unroll
        for (int i = 0; i < 4; i++) acc[nt][i] = 0.f;

    const uint32_t a_base = smem_u32(smc + G2_A) + w * 8192;
    const uint32_t b_base = smem_u32(smc + G2_B);

    const int glr = lane >> 1, ghalf = lane & 1;   // gather: row, 128B half
    const int idx_base = (w * 16 + glr) * KNB;
    const uint32_t grow = a_base + glr * 256;
    const uint32_t gswz = (uint32_t)((glr & 7) << 5);
    const uint32_t bthr = (uint32_t)t * 16;        // this thread's B copy slot

    // prologue: issue k=0 and k=1 (A gather + B tile in one group each)
    #pragma unroll
    for (int kp = 0; kp < 2; kp++) {
        const char* asrc = (const char*)(g_h1pack + (size_t)s_idx[idx_base + kp] * C_MID)
                           + ghalf * 128;
        #pragma unroll
        for (int i = 0; i < 8; i++) {
            uint32_t off = ((uint32_t)(ghalf * 128 + i * 16)) ^ gswz;
            cp_async16(grow + kp * 4096 + off, asrc + i * 16);
        }
        const char* bhsrc = (const char*)(&g_w2f[0][(size_t)kp * 512]);
        const char* blsrc = (const char*)(&g_w2f[1][(size_t)kp * 512]);
        uint32_t bdst = b_base + kp * 16384 + bthr;
        cp_async16(bdst,               bhsrc + bthr);
        cp_async16(bdst + 4096,        bhsrc + bthr + 4096);
        cp_async16(bdst + 8192,        blsrc + bthr);
        cp_async16(bdst + 12288,       blsrc + bthr + 4096);
        CP_COMMIT();
    }

    const int fr = lane >> 2;                       // fragment row
    const uint32_t frswz = (uint32_t)((fr & 7) << 5);
    const uint32_t cbyte0 = (uint32_t)((lane & 3) * 8);
    const uint32_t bl16 = (uint32_t)lane * 16;

    #pragma unroll 1
    for (int k = 0; k < KNB; k++) {
        const uint32_t a_st = a_base + (k & 1) * 4096;
        const uint32_t b_st = b_base + (k & 1) * 16384;
        if (k == KNB - 1) { CP_WAIT0(); } else { CP_WAIT1(); }
        __syncthreads();   // cp.async writes visible to all lanes

        #pragma unroll
        for (int kk = 0; kk < 4; kk++) {
            uint32_t cb = cbyte0 + kk * 64;
            uint2 u00 = lds64(a_st + fr * 256       + (cb ^ frswz));
            uint2 u10 = lds64(a_st + (fr + 8) * 256 + (cb ^ frswz));
            uint2 u01 = lds64(a_st + fr * 256       + ((cb + 32) ^ frswz));
            uint2 u11 = lds64(a_st + (fr + 8) * 256 + ((cb + 32) ^ frswz));
            uint32_t ah[4], al[4];
            ah[0] = __byte_perm(u00.x, u00.y, 0x7632);
            ah[1] = __byte_perm(u10.x, u10.y, 0x7632);
            ah[2] = __byte_perm(u01.x, u01.y, 0x7632);
            ah[3] = __byte_perm(u11.x, u11.y, 0x7632);
            al[0] = __byte_perm(u00.x, u00.y, 0x5410);
            al[1] = __byte_perm(u10.x, u10.y, 0x5410);
            al[2] = __byte_perm(u01.x, u01.y, 0x5410);
            al[3] = __byte_perm(u11.x, u11.y, 0x5410);
            #pragma unroll
            for (int j = 0; j < 4; j++) {
                uint32_t boff = (uint32_t)((kk * 4 + j) * 512) + bl16;
                uint4 Bh = lds128(b_st + boff);
                uint4 Bl = lds128(b_st + 8192 + boff);
                mma16816(acc[2 * j],     ah, Bh.x, Bh.y);
                mma16816(acc[2 * j + 1], ah, Bh.z, Bh.w);
                mma16816(acc[2 * j],     al, Bh.x, Bh.y);
                mma16816(acc[2 * j + 1], al, Bh.z, Bh.w);
                mma16816(acc[2 * j],     ah, Bl.x, Bl.y);
                mma16816(acc[2 * j + 1], ah, Bl.z, Bl.w);
            }
        }
        __syncthreads();   // all warps done reading A+B stage before overwrite
        if (k + 2 < KNB) {
            const char* asrc = (const char*)(g_h1pack +
                               (size_t)s_idx[idx_base + k + 2] * C_MID) + ghalf * 128;
            const uint32_t dstrow = a_st + glr * 256;
            #pragma unroll
            for (int i = 0; i < 8; i++) {
                uint32_t off = ((uint32_t)(ghalf * 128 + i * 16)) ^ gswz;
                cp_async16(dstrow + off, asrc + i * 16);
            }
            const char* bhsrc = (const char*)(&g_w2f[0][(size_t)(k + 2) * 512]);
            const char* blsrc = (const char*)(&g_w2f[1][(size_t)(k + 2) * 512]);
            uint32_t bdst = b_st + bthr;
            cp_async16(bdst,         bhsrc + bthr);
            cp_async16(bdst + 4096,  bhsrc + bthr + 4096);
            cp_async16(bdst + 8192,  blsrc + bthr);
            cp_async16(bdst + 12288, blsrc + bthr + 4096);
            CP_COMMIT();
        }
    }

    // --- epilogue: store y2 + fused stats2 ---
    const int rA = w * 16 + (lane >> 2);
    const int nodeA = n0 + rA, nodeB = nodeA + 8;
    const bool okA = nodeA < N_NODES, okB = nodeB < N_NODES;
    const int col0 = (lane & 3) * 2;
    #pragma unroll
    for (int nt = 0; nt < 8; nt++) {
        int c = nt * 8 + col0;
        if (okA) *(float2*)(g_y2 + (size_t)nodeA * C_MID + c) = make_float2(acc[nt][0], acc[nt][1]);
        if (okB) *(float2*)(g_y2 + (size_t)nodeB * C_MID + c) = make_float2(acc[nt][2], acc[nt][3]);
        float v0 = okA ? acc[nt][0] : 0.f, v1 = okA ? acc[nt][1] : 0.f;
        float v2 = okB ? acc[nt][2] : 0.f, v3 = okB ? acc[nt][3] : 0.f;
        float s0 = v0 + v2, s1 = v1 + v3;
        float q0 = v0 * v0 + v2 * v2, q1 = v1 * v1 + v3 * v3;
        #pragma unroll
        for (int o = 4; o < 32; o <<= 1) {
            s0 += __shfl_xor_sync(0xFFFFFFFF, s0, o);
            s1 += __shfl_xor_sync(0xFFFFFFFF, s1, o);
            q0 += __shfl_xor_sync(0xFFFFFFFF, q0, o);
            q1 += __shfl_xor_sync(0xFFFFFFFF, q1, o);
        }
        if (lane < 4) {
            atomicAdd(&s_sum[c],     s0);
            atomicAdd(&s_sum[c + 1], s1);
            atomicAdd(&s_sq[c],      q0);
            atomicAdd(&s_sq[c + 1],  q1);
        }
    }
    __syncthreads();
    if (t < 64) {
        atomicAdd(&g_stats[128 + t], s_sum[t]);
        atomicAdd(&g_stats[192 + t], s_sq[t]);
    }
}

// ---------------- GEMM3 (warp MMA): y3 = relu(bn2(y2)) @ W3 -----------------
#define G3_A    0
#define G3_SUM  16384
#define G3_SC2  (G3_SUM + 2048)
#define G3_SMEM (G3_SC2 + 512)
__global__ __launch_bounds__(256, 2)
void gemm3_mma_kernel(const float* __restrict__ gamma2, const float* __restrict__ beta2) {
    extern __shared__ char smc[];
    float* s_sum = (float*)(smc + G3_SUM);
    float* s_sq  = s_sum + 256;
    float* s_sc2 = (float*)(smc + G3_SC2);
    float* s_sh2 = s_sc2 + 64;
    const int t = threadIdx.x, w = t >> 5, lane = t & 31;
    const int n0 = blockIdx.x * 64;

    if (t < 256) { s_sum[t] = 0.f; s_sq[t] = 0.f; }
    if (t < 64) {
        const float inv_n = 1.0f / (float)N_NODES;
        float mean = g_stats[128 + t] * inv_n;
        float var  = g_stats[192 + t] * inv_n - mean * mean;
        float sc   = gamma2[t] * rsqrtf(var + BN_EPS);
        s_sc2[t] = sc;
        s_sh2[t] = beta2[t] - mean * sc;
    }
    __syncthreads();

    {
        const int r = t >> 2, q = t & 3;
        const int g = r >> 4, lr = r & 15;
        char* A_hi = smc + G3_A + g * 4096;
        char* A_lo = A_hi + 2048;
        const float4* src = (const float4*)(g_y2 + (size_t)(n0 + r) * C_MID + q * 16);
        #pragma unroll
        for (int i = 0; i < 4; i++) {
            float4 v = __ldg(src + i);
            int c = q * 16 + i * 4;
            float h0 = fmaxf(fmaf(v.x, s_sc2[c + 0], s_sh2[c + 0]), 0.f);
            float h1 = fmaxf(fmaf(v.y, s_sc2[c + 1], s_sh2[c + 1]), 0.f);
            float h2 = fmaxf(fmaf(v.z, s_sc2[c + 2], s_sh2[c + 2]), 0.f);
            float h3 = fmaxf(fmaf(v.w, s_sc2[c + 3], s_sh2[c + 3]), 0.f);
            unsigned short ha, la, hb, lb, hc, lc, hd, ld;
            bf16split(h0, ha, la);
            bf16split(h1, hb, lb);
            bf16split(h2, hc, lc);
            bf16split(h3, hd, ld);
            uint32_t off = sw128((uint32_t)(lr * 128 + q * 32 + i * 8));
            *(uint2*)(A_hi + off) = make_uint2(((uint32_t)hb << 16) | ha,
                                               ((uint32_t)hd << 16) | hc);
            *(uint2*)(A_lo + off) = make_uint2(((uint32_t)lb << 16) | la,
                                               ((uint32_t)ld << 16) | lc);
        }
    }
    __syncthreads();

    const int g = w >> 1, ch = w & 1;
    const uint32_t a_hi_u = smem_u32(smc + G3_A + g * 4096);
    const uint32_t a_lo_u = a_hi_u + 2048;

    float acc[16][4];
    #pragma unroll
    for (int nt = 0; nt < 16; nt++)
        #pragma unroll
        for (int i = 0; i < 4; i++) acc[nt][i] = 0.f;

    #pragma unroll
    for (int kk = 0; kk < 4; kk++) {
        uint32_t ah[4], al[4];
        uint32_t aoff = sw128((uint32_t)((lane & 15) * 128 + kk * 32 + (lane >> 4) * 16));
        ldsm4(ah, a_hi_u + aoff);
        ldsm4(al, a_lo_u + aoff);
        #pragma unroll
        for (int j = 0; j < 8; j++) {
            int jg = ch * 8 + j;
            uint4 Bh = __ldg(&g_w3f[0][(kk * 16 + jg) * 32 + lane]);
            uint4 Bl = __ldg(&g_w3f[1][(kk * 16 + jg) * 32 + lane]);
            mma16816(acc[2 * j],     ah, Bh.x, Bh.y);
            mma16816(acc[2 * j + 1], ah, Bh.z, Bh.w);
            mma16816(acc[2 * j],     al, Bh.x, Bh.y);
            mma16816(acc[2 * j + 1], al, Bh.z, Bh.w);
            mma16816(acc[2 * j],     ah, Bl.x, Bl.y);
            mma16816(acc[2 * j + 1], ah, Bl.z, Bl.w);
        }
    }

    const int rA = g * 16 + (lane >> 2);
    const int nodeA = n0 + rA, nodeB = nodeA + 8;
    const int col0 = ch * 128 + (lane & 3) * 2;
    #pragma unroll
    for (int nt = 0; nt < 16; nt++) {
        int c = col0 + nt * 8;
        *(float2*)(g_y3 + (size_t)nodeA * C_INN + c) = make_float2(acc[nt][0], acc[nt][1]);
        *(float2*)(g_y3 + (size_t)nodeB * C_INN + c) = make_float2(acc[nt][2], acc[nt][3]);
        float s0 = acc[nt][0] + acc[nt][2], s1 = acc[nt][1] + acc[nt][3];
        float q0 = acc[nt][0] * acc[nt][0] + acc[nt][2] * acc[nt][2];
        float q1 = acc[nt][1] * acc[nt][1] + acc[nt][3] * acc[nt][3];
        #pragma unroll
        for (int o = 4; o < 32; o <<= 1) {
            s0 += __shfl_xor_sync(0xFFFFFFFF, s0, o);
            s1 += __shfl_xor_sync(0xFFFFFFFF, s1, o);
            q0 += __shfl_xor_sync(0xFFFFFFFF, q0, o);
            q1 += __shfl_xor_sync(0xFFFFFFFF, q1, o);
        }
        if (lane < 4) {
            atomicAdd(&s_sum[c],     s0);
            atomicAdd(&s_sum[c + 1], s1);
            atomicAdd(&s_sq[c],      q0);
            atomicAdd(&s_sq[c + 1],  q1);
        }
    }
    __syncthreads();
    if (t < 256) {
        atomicAdd(&g_stats[256 + t], s_sum[t]);
        atomicAdd(&g_stats[512 + t], s_sq[t]);
    }
}

// ---------------- epilogue: per-block BN3 finalize + residual + relu --------
__global__ void epilogue_kernel(const float* __restrict__ x,
                                const float* __restrict__ gamma3,
                                const float* __restrict__ beta3,
                                float* __restrict__ out) {
    __shared__ float s_sc[256], s_sh[256];
    const int tt = threadIdx.x;
    {
        const float inv_n = 1.0f / (float)N_NODES;
        float mean = g_stats[256 + tt] * inv_n;
        float var  = g_stats[512 + tt] * inv_n - mean * mean;
        float sc   = gamma3[tt] * rsqrtf(var + BN_EPS);
        s_sc[tt] = sc;
        s_sh[tt] = beta3[tt] - mean * sc;
    }
    __syncthreads();
    size_t i4 = (size_t)blockIdx.x * blockDim.x + tt;
    if (i4 >= (size_t)N_NODES * (C_INN / 4)) return;
    int c = ((int)(i4 & 63)) << 2;
    float4 y  = ((const float4*)g_y3)[i4];
    float4 xi = ((const float4*)x)[i4];
    float4 o;
    o.x = fmaxf(fmaf(y.x, s_sc[c + 0], s_sh[c + 0]) + xi.x, 0.f);
    o.y = fmaxf(fmaf(y.y, s_sc[c + 1], s_sh[c + 1]) + xi.y, 0.f);
    o.z = fmaxf(fmaf(y.z, s_sc[c + 2], s_sh[c + 2]) + xi.z, 0.f);
    o.w = fmaxf(fmaf(y.w, s_sc[c + 3], s_sh[c + 3]) + xi.w, 0.f);
    ((float4*)out)[i4] = o;
}

// ---------------- launch (gemm2 = our #4 -> profiled by ncu -s5) ------------
extern "C" void kernel_launch(void* const* d_in, const int* in_sizes, int n_in,
                              void* d_out, int out_size) {
    const float* x     = (const float*)d_in[0];
    const int*   neigh = (const int*)d_in[1];
    const float* W1 = (const float*)d_in[3];
    const float* g1 = (const float*)d_in[4];
    const float* b1 = (const float*)d_in[5];
    const float* W2 = (const float*)d_in[6];
    const float* g2 = (const float*)d_in[7];
    const float* b2 = (const float*)d_in[8];
    const float* W3 = (const float*)d_in[9];
    const float* g3 = (const float*)d_in[10];
    const float* b3 = (const float*)d_in[11];
    float* out = (float*)d_out;

    cudaFuncSetAttribute(gemm1_mma_kernel, cudaFuncAttributeMaxDynamicSharedMemorySize, G1_SMEM);
    cudaFuncSetAttribute(gemm2_mma_kernel, cudaFuncAttributeMaxDynamicSharedMemorySize, G2_SMEM);
    cudaFuncSetAttribute(gemm3_mma_kernel, cudaFuncAttributeMaxDynamicSharedMemorySize, G3_SMEM);

    convert_all_kernel<<<35, 512>>>(W1, W2, W3);                          // 1
    gemm1_mma_kernel<<<(N_NODES + 127) / 128, 256, G1_SMEM>>>(x);         // 2
    convert_h1_kernel<<<(N_NODES * (C_MID / 4) + 255) / 256, 256>>>(g1, b1); // 3
    gemm2_mma_kernel<<<G2_BLOCKS, 256, G2_SMEM>>>(neigh);                 // 4 <- profiled
    gemm3_mma_kernel<<<N_NODES / 64, 256, G3_SMEM>>>(g2, b2);             // 5
    epilogue_kernel<<<(N_NODES * (C_INN / 4) + 255) / 256, 256>>>(x, g3, b3, out); // 6
}

// round 16
// speedup vs baseline: 1.2262x; 1.2262x over previous
#include <cuda_runtime.h>
#include <cuda_fp16.h>
#include <math.h>
#include <stdint.h>

#define N_NODES 200000
#define C_INN   256
#define C_MID   64
#define KNB     27
#define BN_EPS  1e-3f

// ---------------- scratch (device globals; no allocations allowed) ----------
__device__ float g_y1[(size_t)N_NODES * C_MID];   // x@W1 (fp32)
__device__ float g_y2[(size_t)N_NODES * C_MID];   // gathered conv out
__device__ float g_y3[(size_t)N_NODES * C_INN];   // h2@W3
__device__ unsigned int g_h1pack[(size_t)N_NODES * C_MID];   // (hi<<16)|lo fp16 of relu(bn1(y1))
// weights in m16n8k16 B-fragment order (fp16 hi only; 2-term split):
__device__ __align__(16) uint4 g_w2f[KNB * 4 * 4 * 32];
__device__ __align__(16) uint4 g_w1f[16 * 4 * 32];
__device__ __align__(16) uint4 g_w3f[4 * 16 * 32];
// stats layout: [0:64) sum1 [64:128) sq1 [128:192) sum2 [192:256) sq2
//               [256:512) sum3 [512:768) sq3
__device__ float g_stats[768];

// ======================= warp-MMA helpers (plain sm_103 PTX) =================
__device__ __forceinline__ uint32_t smem_u32(const void* p) {
    uint32_t a;
    asm("{ .reg .u64 t; cvta.to.shared.u64 t, %1; cvt.u32.u64 %0, t; }" : "=r"(a) : "l"(p));
    return a;
}
__device__ __forceinline__ uint32_t sw128(uint32_t off) { return off ^ ((off >> 3) & 0x70); }

__device__ __forceinline__ void ldsm4(uint32_t* r, uint32_t addr) {
    asm volatile("ldmatrix.sync.aligned.m8n8.x4.shared.b16 {%0,%1,%2,%3}, [%4];"
                 : "=r"(r[0]), "=r"(r[1]), "=r"(r[2]), "=r"(r[3]) : "r"(addr));
}
// fp16 inputs, fp32 accumulate
__device__ __forceinline__ void mma16816(float* d, const uint32_t* a, uint32_t b0, uint32_t b1) {
    asm volatile("mma.sync.aligned.m16n8k16.row.col.f32.f16.f16.f32 "
                 "{%0,%1,%2,%3}, {%4,%5,%6,%7}, {%8,%9}, {%0,%1,%2,%3};"
                 : "+f"(d[0]), "+f"(d[1]), "+f"(d[2]), "+f"(d[3])
                 : "r"(a[0]), "r"(a[1]), "r"(a[2]), "r"(a[3]), "r"(b0), "r"(b1));
}
__device__ __forceinline__ void f16split(float v, unsigned short& h, unsigned short& l) {
    __half hb = __float2half(v);
    h = __half_as_ushort(hb);
    l = __half_as_ushort(__float2half(v - __half2float(hb)));
}
__device__ __forceinline__ void cp_async16(uint32_t dst, const void* src) {
    asm volatile("cp.async.cg.shared.global [%0], [%1], 16;" :: "r"(dst), "l"(src));
}
#define CP_COMMIT() asm volatile("cp.async.commit_group;" ::: "memory")
#define CP_WAIT1()  asm volatile("cp.async.wait_group 1;" ::: "memory")
#define CP_WAIT0()  asm volatile("cp.async.wait_group 0;" ::: "memory")

__device__ __forceinline__ uint2 lds64(uint32_t addr) {
    uint2 v;
    asm volatile("ld.shared.v2.u32 {%0,%1}, [%2];" : "=r"(v.x), "=r"(v.y) : "r"(addr));
    return v;
}

// -------- weight fragment packer (m16n8k16 B-frag order; fp16 hi only) ------
__device__ __forceinline__ void pack_frag(const float* __restrict__ W, int ldw,
                                          int c0, int n0, uint4* hi4) {
    unsigned int hi[4];
    #pragma unroll
    for (int q = 0; q < 4; q++) {
        int c = c0 + (q & 1) * 8;
        int n = n0 + (q >> 1) * 8;
        __half h0 = __float2half(W[c * ldw + n]);
        __half h1 = __float2half(W[(c + 1) * ldw + n]);
        hi[q] = ((unsigned int)__half_as_ushort(h1) << 16) | __half_as_ushort(h0);
    }
    *hi4 = make_uint4(hi[0], hi[1], hi[2], hi[3]);
}

// ---------------- convert_all: pack W1/W2/W3 frags + zero stats -------------
__global__ void convert_all_kernel(const float* __restrict__ W1,
                                   const float* __restrict__ W2,
                                   const float* __restrict__ W3) {
    int b = blockIdx.x, t = threadIdx.x;    // 512 threads
    if (b == 0) {
        for (int i = t; i < 768; i += 512) g_stats[i] = 0.f;
    }
    if (b < 27) {
        int kk = t >> 7, j = (t >> 5) & 3, lane = t & 31;
        int idx = ((b * 4 + kk) * 4 + j) * 32 + lane;
        pack_frag(W2 + (size_t)b * 4096, 64,
                  kk * 16 + (lane & 3) * 2, j * 16 + (lane >> 2), &g_w2f[idx]);
    } else if (b < 31) {
        int gt = (b - 27) * 512 + t;
        int kk = gt >> 7, j = (gt >> 5) & 3, lane = gt & 31;
        int idx = (kk * 4 + j) * 32 + lane;
        pack_frag(W1, 64, kk * 16 + (lane & 3) * 2, j * 16 + (lane >> 2), &g_w1f[idx]);
    } else {
        int gt = (b - 31) * 512 + t;
        int kk = gt >> 9, j = (gt >> 5) & 15, lane = gt & 31;
        int idx = (kk * 16 + j) * 32 + lane;
        pack_frag(W3, 256, kk * 16 + (lane & 3) * 2, j * 16 + (lane >> 2), &g_w3f[idx]);
    }
}

// ---------------- GEMM1 (warp MMA, fp16 2-term): y1 = x @ W1 + stats1 -------
#define G1_SUM  32768
#define G1_SMEM (G1_SUM + 512)
__global__ __launch_bounds__(256, 2)
void gemm1_mma_kernel(const float* __restrict__ x) {
    extern __shared__ char smc[];
    float* s_sum = (float*)(smc + G1_SUM);
    float* s_sq  = s_sum + 64;
    const int t = threadIdx.x, w = t >> 5, lane = t & 31;
    const int n0 = blockIdx.x * 128;
    if (t < 64) { s_sum[t] = 0.f; s_sq[t] = 0.f; }
    __syncthreads();

    float acc[8][4];
    #pragma unroll
    for (int nt = 0; nt < 8; nt++)
        #pragma unroll
        for (int i = 0; i < 4; i++) acc[nt][i] = 0.f;

    char* Aw_hi = smc + w * 4096;
    char* Aw_lo = Aw_hi + 2048;
    const uint32_t a_hi_u = smem_u32(Aw_hi);
    const uint32_t a_lo_u = a_hi_u + 2048;

    const int glr = lane >> 1, ghalf = lane & 1;
    const int row = n0 + w * 16 + glr;
    const int rowc = row < N_NODES ? row : N_NODES - 1;
    const float4* xsrc = (const float4*)(x + (size_t)rowc * C_INN + ghalf * 32);

    float4 f[8];
    #pragma unroll
    for (int i = 0; i < 8; i++) f[i] = __ldg(xsrc + i);

    #pragma unroll
    for (int kc = 0; kc < 4; kc++) {
        #pragma unroll
        for (int i = 0; i < 8; i++) {
            unsigned short hx, lx, hy, ly, hz, lz, hw, lw;
            f16split(f[i].x, hx, lx);
            f16split(f[i].y, hy, ly);
            f16split(f[i].z, hz, lz);
            f16split(f[i].w, hw, lw);
            uint32_t off = sw128((uint32_t)(glr * 128 + ghalf * 64 + i * 8));
            *(uint2*)(Aw_hi + off) = make_uint2(((uint32_t)hy << 16) | hx,
                                                ((uint32_t)hw << 16) | hz);
            *(uint2*)(Aw_lo + off) = make_uint2(((uint32_t)ly << 16) | lx,
                                                ((uint32_t)lw << 16) | lz);
        }
        __syncwarp();
        if (kc < 3) {
            #pragma unroll
            for (int i = 0; i < 8; i++) f[i] = __ldg(xsrc + (kc + 1) * 16 + i);
        }
        #pragma unroll
        for (int kk = 0; kk < 4; kk++) {
            uint32_t ah[4], al[4];
            uint32_t aoff = sw128((uint32_t)((lane & 15) * 128 + kk * 32 + (lane >> 4) * 16));
            ldsm4(ah, a_hi_u + aoff);
            ldsm4(al, a_lo_u + aoff);
            #pragma unroll
            for (int j = 0; j < 4; j++) {
                uint4 Bh = __ldg(&g_w1f[((kc * 4 + kk) * 4 + j) * 32 + lane]);
                mma16816(acc[2 * j],     ah, Bh.x, Bh.y);
                mma16816(acc[2 * j + 1], ah, Bh.z, Bh.w);
                mma16816(acc[2 * j],     al, Bh.x, Bh.y);
                mma16816(acc[2 * j + 1], al, Bh.z, Bh.w);
            }
        }
        __syncwarp();
    }

    const int rA = w * 16 + (lane >> 2);
    const int nodeA = n0 + rA, nodeB = nodeA + 8;
    const bool okA = nodeA < N_NODES, okB = nodeB < N_NODES;
    const int col0 = (lane & 3) * 2;
    #pragma unroll
    for (int nt = 0; nt < 8; nt++) {
        int c = nt * 8 + col0;
        if (okA) *(float2*)(g_y1 + (size_t)nodeA * C_MID + c) = make_float2(acc[nt][0], acc[nt][1]);
        if (okB) *(float2*)(g_y1 + (size_t)nodeB * C_MID + c) = make_float2(acc[nt][2], acc[nt][3]);
        float v0 = okA ? acc[nt][0] : 0.f, v1 = okA ? acc[nt][1] : 0.f;
        float v2 = okB ? acc[nt][2] : 0.f, v3 = okB ? acc[nt][3] : 0.f;
        float s0 = v0 + v2, s1 = v1 + v3;
        float q0 = v0 * v0 + v2 * v2, q1 = v1 * v1 + v3 * v3;
        #pragma unroll
        for (int o = 4; o < 32; o <<= 1) {
            s0 += __shfl_xor_sync(0xFFFFFFFF, s0, o);
            s1 += __shfl_xor_sync(0xFFFFFFFF, s1, o);
            q0 += __shfl_xor_sync(0xFFFFFFFF, q0, o);
            q1 += __shfl_xor_sync(0xFFFFFFFF, q1, o);
        }
        if (lane < 4) {
            atomicAdd(&s_sum[c],     s0);
            atomicAdd(&s_sum[c + 1], s1);
            atomicAdd(&s_sq[c],      q0);
            atomicAdd(&s_sq[c + 1],  q1);
        }
    }
    __syncthreads();
    if (t < 64) {
        atomicAdd(&g_stats[t],      s_sum[t]);
        atomicAdd(&g_stats[64 + t], s_sq[t]);
    }
}

// ---------------- convert h1: per-block BN1 finalize + pack fp16 hi/lo ------
__global__ void convert_h1_kernel(const float* __restrict__ gamma,
                                  const float* __restrict__ beta) {
    __shared__ float s_sc[64], s_sh[64];
    const int tt = threadIdx.x;
    if (tt < 64) {
        const float inv_n = 1.0f / (float)N_NODES;
        float mean = g_stats[tt] * inv_n;
        float var  = g_stats[64 + tt] * inv_n - mean * mean;
        float sc   = gamma[tt] * rsqrtf(var + BN_EPS);
        s_sc[tt] = sc;
        s_sh[tt] = beta[tt] - mean * sc;
    }
    __syncthreads();
    size_t i = (size_t)blockIdx.x * blockDim.x + tt;   // one float4
    if (i >= (size_t)N_NODES * (C_MID / 4)) return;
    int c0 = ((int)(i & 15)) << 2;
    float4 y = ((const float4*)g_y1)[i];
    float v[4] = {y.x, y.y, y.z, y.w};
    uint4 o;
    unsigned int* op = (unsigned int*)&o;
    #pragma unroll
    for (int j = 0; j < 4; j++) {
        float h = fmaxf(fmaf(v[j], s_sc[c0 + j], s_sh[c0 + j]), 0.f);
        unsigned short hb, lb;
        f16split(h, hb, lb);
        op[j] = ((unsigned int)hb << 16) | lb;
    }
    ((uint4*)g_h1pack)[i] = o;
}

// ---------------- GEMM2 v7: 32 rows/warp (R10 base) + fp16 2-term -----------
// CTA = 256 rows, 8 warps x 32 rows. Per-warp private A stages (32 rows x
// 256B packed hi|lo, XOR-swizzled), double-buffered cp.async (lane = row).
// 2-term split: D = Ah*Bh + Al*Bh -> 8 MMAs per Bh load (B table halved,
// MMA count -33% vs R10). Warp-private stages: wait_group + __syncwarp.
#define G2_IDX   0
#define G2_A     27648                 // 8 warps x 2 stages x 8192
#define G2_SUM   (G2_A + 131072)       // 158720
#define G2_SMEM  (G2_SUM + 512)        // 159232
#define G2_BLOCKS ((N_NODES + 255) / 256)   // 782

__global__ __launch_bounds__(256, 1)
void gemm2_mma_kernel(const int* __restrict__ neigh) {
    extern __shared__ char smc[];
    int*   s_idx = (int*)(smc + G2_IDX);
    float* s_sum = (float*)(smc + G2_SUM);
    float* s_sq  = s_sum + 64;

    const int t = threadIdx.x, w = t >> 5, lane = t & 31;
    const int n0 = blockIdx.x * 256;

    for (int i = t; i < 256 * KNB; i += 256) {
        size_t gi = (size_t)n0 * KNB + i;
        s_idx[i] = (gi < (size_t)N_NODES * KNB) ? neigh[gi] : 0;
    }
    if (t < 64) { s_sum[t] = 0.f; s_sq[t] = 0.f; }
    __syncthreads();

    float acc0[8][4], acc1[8][4];
    #pragma unroll
    for (int nt = 0; nt < 8; nt++)
        #pragma unroll
        for (int i = 0; i < 4; i++) { acc0[nt][i] = 0.f; acc1[nt][i] = 0.f; }

    const uint32_t a_base = smem_u32(smc + G2_A) + w * 16384;

    // gather: lane owns one full row (256B = 16 cp.async16)
    const int idx_base = (w * 32 + lane) * KNB;
    const uint32_t grow = a_base + lane * 256;
    const uint32_t gswz = (uint32_t)((lane & 7) << 5);

    #pragma unroll
    for (int kp = 0; kp < 2; kp++) {
        const char* src = (const char*)(g_h1pack + (size_t)s_idx[idx_base + kp] * C_MID);
        #pragma unroll
        for (int i = 0; i < 16; i++) {
            uint32_t off = ((uint32_t)(i * 16)) ^ gswz;
            cp_async16(grow + kp * 8192 + off, src + i * 16);
        }
        CP_COMMIT();
    }

    const int fr = lane >> 2;                       // fragment row 0..7
    const uint32_t frswz = (uint32_t)((fr & 7) << 5);
    const uint32_t cbyte0 = (uint32_t)((lane & 3) * 8);

    #pragma unroll 1
    for (int k = 0; k < KNB; k++) {
        const uint32_t st = a_base + (k & 1) * 8192;
        if (k == KNB - 1) { CP_WAIT0(); } else { CP_WAIT1(); }
        __syncwarp();   // warp-private stage

        const uint4* bh_k = &g_w2f[(size_t)k * 512 + lane];
        #pragma unroll
        for (int kk = 0; kk < 4; kk++) {
            uint32_t cb = cbyte0 + kk * 64;
            uint2 u00 = lds64(st + fr * 256        + (cb ^ frswz));
            uint2 u10 = lds64(st + (fr + 8) * 256  + (cb ^ frswz));
            uint2 u01 = lds64(st + fr * 256        + ((cb + 32) ^ frswz));
            uint2 u11 = lds64(st + (fr + 8) * 256  + ((cb + 32) ^ frswz));
            uint2 v00 = lds64(st + (fr + 16) * 256 + (cb ^ frswz));
            uint2 v10 = lds64(st + (fr + 24) * 256 + (cb ^ frswz));
            uint2 v01 = lds64(st + (fr + 16) * 256 + ((cb + 32) ^ frswz));
            uint2 v11 = lds64(st + (fr + 24) * 256 + ((cb + 32) ^ frswz));
            uint32_t ah0[4], al0[4], ah1[4], al1[4];
            ah0[0] = __byte_perm(u00.x, u00.y, 0x7632);
            ah0[1] = __byte_perm(u10.x, u10.y, 0x7632);
            ah0[2] = __byte_perm(u01.x, u01.y, 0x7632);
            ah0[3] = __byte_perm(u11.x, u11.y, 0x7632);
            al0[0] = __byte_perm(u00.x, u00.y, 0x5410);
            al0[1] = __byte_perm(u10.x, u10.y, 0x5410);
            al0[2] = __byte_perm(u01.x, u01.y, 0x5410);
            al0[3] = __byte_perm(u11.x, u11.y, 0x5410);
            ah1[0] = __byte_perm(v00.x, v00.y, 0x7632);
            ah1[1] = __byte_perm(v10.x, v10.y, 0x7632);
            ah1[2] = __byte_perm(v01.x, v01.y, 0x7632);
            ah1[3] = __byte_perm(v11.x, v11.y, 0x7632);
            al1[0] = __byte_perm(v00.x, v00.y, 0x5410);
            al1[1] = __byte_perm(v10.x, v10.y, 0x5410);
            al1[2] = __byte_perm(v01.x, v01.y, 0x5410);
            al1[3] = __byte_perm(v11.x, v11.y, 0x5410);
            #pragma unroll
            for (int j = 0; j < 4; j++) {
                uint4 Bh = __ldg(bh_k + (kk * 4 + j) * 32);
                mma16816(acc0[2 * j],     ah0, Bh.x, Bh.y);
                mma16816(acc1[2 * j],     ah1, Bh.x, Bh.y);
                mma16816(acc0[2 * j + 1], ah0, Bh.z, Bh.w);
                mma16816(acc1[2 * j + 1], ah1, Bh.z, Bh.w);
                mma16816(acc0[2 * j],     al0, Bh.x, Bh.y);
                mma16816(acc1[2 * j],     al1, Bh.x, Bh.y);
                mma16816(acc0[2 * j + 1], al0, Bh.z, Bh.w);
                mma16816(acc1[2 * j + 1], al1, Bh.z, Bh.w);
            }
        }
        __syncwarp();
        if (k + 2 < KNB) {
            const char* src = (const char*)(g_h1pack +
                              (size_t)s_idx[idx_base + k + 2] * C_MID);
            const uint32_t dstrow = st + lane * 256;
            #pragma unroll
            for (int i = 0; i < 16; i++) {
                uint32_t off = ((uint32_t)(i * 16)) ^ gswz;
                cp_async16(dstrow + off, src + i * 16);
            }
            CP_COMMIT();
        }
    }

    // --- epilogue: store y2 + fused stats2 (both tiles) ---
    const int r0n = n0 + w * 32 + fr;
    const int nA0 = r0n, nB0 = r0n + 8, nA1 = r0n + 16, nB1 = r0n + 24;
    const bool oA0 = nA0 < N_NODES, oB0 = nB0 < N_NODES;
    const bool oA1 = nA1 < N_NODES, oB1 = nB1 < N_NODES;
    const int col0 = (lane & 3) * 2;
    #pragma unroll
    for (int nt = 0; nt < 8; nt++) {
        int c = nt * 8 + col0;
        if (oA0) *(float2*)(g_y2 + (size_t)nA0 * C_MID + c) = make_float2(acc0[nt][0], acc0[nt][1]);
        if (oB0) *(float2*)(g_y2 + (size_t)nB0 * C_MID + c) = make_float2(acc0[nt][2], acc0[nt][3]);
        if (oA1) *(float2*)(g_y2 + (size_t)nA1 * C_MID + c) = make_float2(acc1[nt][0], acc1[nt][1]);
        if (oB1) *(float2*)(g_y2 + (size_t)nB1 * C_MID + c) = make_float2(acc1[nt][2], acc1[nt][3]);
        float a0 = oA0 ? acc0[nt][0] : 0.f, a1 = oA0 ? acc0[nt][1] : 0.f;
        float b0 = oB0 ? acc0[nt][2] : 0.f, b1 = oB0 ? acc0[nt][3] : 0.f;
        float c0v = oA1 ? acc1[nt][0] : 0.f, c1v = oA1 ? acc1[nt][1] : 0.f;
        float d0 = oB1 ? acc1[nt][2] : 0.f, d1 = oB1 ? acc1[nt][3] : 0.f;
        float s0 = a0 + b0 + c0v + d0, s1 = a1 + b1 + c1v + d1;
        float q0 = a0 * a0 + b0 * b0 + c0v * c0v + d0 * d0;
        float q1 = a1 * a1 + b1 * b1 + c1v * c1v + d1 * d1;
        #pragma unroll
        for (int o = 4; o < 32; o <<= 1) {
            s0 += __shfl_xor_sync(0xFFFFFFFF, s0, o);
            s1 += __shfl_xor_sync(0xFFFFFFFF, s1, o);
            q0 += __shfl_xor_sync(0xFFFFFFFF, q0, o);
            q1 += __shfl_xor_sync(0xFFFFFFFF, q1, o);
        }
        if (lane < 4) {
            atomicAdd(&s_sum[c],     s0);
            atomicAdd(&s_sum[c + 1], s1);
            atomicAdd(&s_sq[c],      q0);
            atomicAdd(&s_sq[c + 1],  q1);
        }
    }
    __syncthreads();
    if (t < 64) {
        atomicAdd(&g_stats[128 + t], s_sum[t]);
        atomicAdd(&g_stats[192 + t], s_sq[t]);
    }
}

// ---------------- GEMM3 (warp MMA, fp16 2-term): y3 = relu(bn2(y2)) @ W3 ----
#define G3_A    0
#define G3_SUM  16384
#define G3_SC2  (G3_SUM + 2048)
#define G3_SMEM (G3_SC2 + 512)
__global__ __launch_bounds__(256, 2)
void gemm3_mma_kernel(const float* __restrict__ gamma2, const float* __restrict__ beta2) {
    extern __shared__ char smc[];
    float* s_sum = (float*)(smc + G3_SUM);
    float* s_sq  = s_sum + 256;
    float* s_sc2 = (float*)(smc + G3_SC2);
    float* s_sh2 = s_sc2 + 64;
    const int t = threadIdx.x, w = t >> 5, lane = t & 31;
    const int n0 = blockIdx.x * 64;

    if (t < 256) { s_sum[t] = 0.f; s_sq[t] = 0.f; }
    if (t < 64) {
        const float inv_n = 1.0f / (float)N_NODES;
        float mean = g_stats[128 + t] * inv_n;
        float var  = g_stats[192 + t] * inv_n - mean * mean;
        float sc   = gamma2[t] * rsqrtf(var + BN_EPS);
        s_sc2[t] = sc;
        s_sh2[t] = beta2[t] - mean * sc;
    }
    __syncthreads();

    {
        const int r = t >> 2, q = t & 3;
        const int g = r >> 4, lr = r & 15;
        char* A_hi = smc + G3_A + g * 4096;
        char* A_lo = A_hi + 2048;
        const float4* src = (const float4*)(g_y2 + (size_t)(n0 + r) * C_MID + q * 16);
        #pragma unroll
        for (int i = 0; i < 4; i++) {
            float4 v = __ldg(src + i);
            int c = q * 16 + i * 4;
            float h0 = fmaxf(fmaf(v.x, s_sc2[c + 0], s_sh2[c + 0]), 0.f);
            float h1 = fmaxf(fmaf(v.y, s_sc2[c + 1], s_sh2[c + 1]), 0.f);
            float h2 = fmaxf(fmaf(v.z, s_sc2[c + 2], s_sh2[c + 2]), 0.f);
            float h3 = fmaxf(fmaf(v.w, s_sc2[c + 3], s_sh2[c + 3]), 0.f);
            unsigned short ha, la, hb, lb, hc, lc, hd, ld;
            f16split(h0, ha, la);
            f16split(h1, hb, lb);
            f16split(h2, hc, lc);
            f16split(h3, hd, ld);
            uint32_t off = sw128((uint32_t)(lr * 128 + q * 32 + i * 8));
            *(uint2*)(A_hi + off) = make_uint2(((uint32_t)hb << 16) | ha,
                                               ((uint32_t)hd << 16) | hc);
            *(uint2*)(A_lo + off) = make_uint2(((uint32_t)lb << 16) | la,
                                               ((uint32_t)ld << 16) | lc);
        }
    }
    __syncthreads();

    const int g = w >> 1, ch = w & 1;
    const uint32_t a_hi_u = smem_u32(smc + G3_A + g * 4096);
    const uint32_t a_lo_u = a_hi_u + 2048;

    float acc[16][4];
    #pragma unroll
    for (int nt = 0; nt < 16; nt++)
        #pragma unroll
        for (int i = 0; i < 4; i++) acc[nt][i] = 0.f;

    #pragma unroll
    for (int kk = 0; kk < 4; kk++) {
        uint32_t ah[4], al[4];
        uint32_t aoff = sw128((uint32_t)((lane & 15) * 128 + kk * 32 + (lane >> 4) * 16));
        ldsm4(ah, a_hi_u + aoff);
        ldsm4(al, a_lo_u + aoff);
        #pragma unroll
        for (int j = 0; j < 8; j++) {
            int jg = ch * 8 + j;
            uint4 Bh = __ldg(&g_w3f[(kk * 16 + jg) * 32 + lane]);
            mma16816(acc[2 * j],     ah, Bh.x, Bh.y);
            mma16816(acc[2 * j + 1], ah, Bh.z, Bh.w);
            mma16816(acc[2 * j],     al, Bh.x, Bh.y);
            mma16816(acc[2 * j + 1], al, Bh.z, Bh.w);
        }
    }

    const int rA = g * 16 + (lane >> 2);
    const int nodeA = n0 + rA, nodeB = nodeA + 8;
    const int col0 = ch * 128 + (lane & 3) * 2;
    #pragma unroll
    for (int nt = 0; nt < 16; nt++) {
        int c = col0 + nt * 8;
        *(float2*)(g_y3 + (size_t)nodeA * C_INN + c) = make_float2(acc[nt][0], acc[nt][1]);
        *(float2*)(g_y3 + (size_t)nodeB * C_INN + c) = make_float2(acc[nt][2], acc[nt][3]);
        float s0 = acc[nt][0] + acc[nt][2], s1 = acc[nt][1] + acc[nt][3];
        float q0 = acc[nt][0] * acc[nt][0] + acc[nt][2] * acc[nt][2];
        float q1 = acc[nt][1] * acc[nt][1] + acc[nt][3] * acc[nt][3];
        #pragma unroll
        for (int o = 4; o < 32; o <<= 1) {
            s0 += __shfl_xor_sync(0xFFFFFFFF, s0, o);
            s1 += __shfl_xor_sync(0xFFFFFFFF, s1, o);
            q0 += __shfl_xor_sync(0xFFFFFFFF, q0, o);
            q1 += __shfl_xor_sync(0xFFFFFFFF, q1, o);
        }
        if (lane < 4) {
            atomicAdd(&s_sum[c],     s0);
            atomicAdd(&s_sum[c + 1], s1);
            atomicAdd(&s_sq[c],      q0);
            atomicAdd(&s_sq[c + 1],  q1);
        }
    }
    __syncthreads();
    if (t < 256) {
        atomicAdd(&g_stats[256 + t], s_sum[t]);
        atomicAdd(&g_stats[512 + t], s_sq[t]);
    }
}

// ---------------- epilogue: per-block BN3 finalize + residual + relu --------
__global__ void epilogue_kernel(const float* __restrict__ x,
                                const float* __restrict__ gamma3,
                                const float* __restrict__ beta3,
                                float* __restrict__ out) {
    __shared__ float s_sc[256], s_sh[256];
    const int tt = threadIdx.x;
    {
        const float inv_n = 1.0f / (float)N_NODES;
        float mean = g_stats[256 + tt] * inv_n;
        float var  = g_stats[512 + tt] * inv_n - mean * mean;
        float sc   = gamma3[tt] * rsqrtf(var + BN_EPS);
        s_sc[tt] = sc;
        s_sh[tt] = beta3[tt] - mean * sc;
    }
    __syncthreads();
    size_t i4 = (size_t)blockIdx.x * blockDim.x + tt;
    if (i4 >= (size_t)N_NODES * (C_INN / 4)) return;
    int c = ((int)(i4 & 63)) << 2;
    float4 y  = ((const float4*)g_y3)[i4];
    float4 xi = ((const float4*)x)[i4];
    float4 o;
    o.x = fmaxf(fmaf(y.x, s_sc[c + 0], s_sh[c + 0]) + xi.x, 0.f);
    o.y = fmaxf(fmaf(y.y, s_sc[c + 1], s_sh[c + 1]) + xi.y, 0.f);
    o.z = fmaxf(fmaf(y.z, s_sc[c + 2], s_sh[c + 2]) + xi.z, 0.f);
    o.w = fmaxf(fmaf(y.w, s_sc[c + 3], s_sh[c + 3]) + xi.w, 0.f);
    ((float4*)out)[i4] = o;
}

// ---------------- launch (gemm2 = our #4 -> profiled by ncu -s5) ------------
extern "C" void kernel_launch(void* const* d_in, const int* in_sizes, int n_in,
                              void* d_out, int out_size) {
    const float* x     = (const float*)d_in[0];
    const int*   neigh = (const int*)d_in[1];
    const float* W1 = (const float*)d_in[3];
    const float* g1 = (const float*)d_in[4];
    const float* b1 = (const float*)d_in[5];
    const float* W2 = (const float*)d_in[6];
    const float* g2 = (const float*)d_in[7];
    const float* b2 = (const float*)d_in[8];
    const float* W3 = (const float*)d_in[9];
    const float* g3 = (const float*)d_in[10];
    const float* b3 = (const float*)d_in[11];
    float* out = (float*)d_out;

    cudaFuncSetAttribute(gemm1_mma_kernel, cudaFuncAttributeMaxDynamicSharedMemorySize, G1_SMEM);
    cudaFuncSetAttribute(gemm2_mma_kernel, cudaFuncAttributeMaxDynamicSharedMemorySize, G2_SMEM);
    cudaFuncSetAttribute(gemm3_mma_kernel, cudaFuncAttributeMaxDynamicSharedMemorySize, G3_SMEM);

    convert_all_kernel<<<35, 512>>>(W1, W2, W3);                          // 1
    gemm1_mma_kernel<<<(N_NODES + 127) / 128, 256, G1_SMEM>>>(x);         // 2
    convert_h1_kernel<<<(N_NODES * (C_MID / 4) + 255) / 256, 256>>>(g1, b1); // 3
    gemm2_mma_kernel<<<G2_BLOCKS, 256, G2_SMEM>>>(neigh);                 // 4 <- profiled
    gemm3_mma_kernel<<<N_NODES / 64, 256, G3_SMEM>>>(g2, b2);             // 5
    epilogue_kernel<<<(N_NODES * (C_INN / 4) + 255) / 256, 256>>>(x, g3, b3, out); // 6
}